// round 6
// baseline (speedup 1.0000x reference)
#include <cuda_runtime.h>
#include <math.h>

// Problem constants
#define B 4
#define C 64
#define IC 16
#define H 128
#define W 128
#define DH 64
#define DW 64
#define N 4096          // DH*DW
#define BN_COUNT (B*H*W) // 65536 elems per channel
#define SPLITK 4

typedef unsigned long long u64;

// packed f32x2 helpers (sm_100+): 2 fp32 MACs per fma-pipe issue (SASS FFMA2)
__device__ __forceinline__ u64 fma2(u64 a, u64 b, u64 c) {
    u64 d; asm("fma.rn.f32x2 %0,%1,%2,%3;" : "=l"(d) : "l"(a), "l"(b), "l"(c)); return d;
}
__device__ __forceinline__ u64 mul2(u64 a, u64 b) {
    u64 d; asm("mul.rn.f32x2 %0,%1,%2;" : "=l"(d) : "l"(a), "l"(b)); return d;
}
__device__ __forceinline__ u64 add2(u64 a, u64 b) {
    u64 d; asm("add.rn.f32x2 %0,%1,%2;" : "=l"(d) : "l"(a), "l"(b)); return d;
}

// ------------------------- scratch (static device) -------------------------
__device__ float g_qkv[3 * B * N * IC];            // [which][b*N+n][16]  0=Q 1=K 2=V
__device__ float g_opart[SPLITK * B * N * IC];     // split-K partial O
__device__ float g_lpart[SPLITK * B * N];          // split-K partial l
__device__ float g_y[B * N * IC];                  // merged attention output
__device__ float g_z[B * C * H * W];               // residual sum, pre-BN
__device__ float g_bnpart[B * C * 4 * 2];          // per-(plane,chunk) sum/sumsq
__device__ float g_bnstat[C * 2];                  // mean, rstd

// ------------------- K1: downsample (point-sample odd pixels) + QKV projections -------------------
// jax scale_and_translate, scale=0.5, trans=-0.25  =>  sample_f = 2*o + 1 (exact hit)
__global__ void k_down_proj(const float* __restrict__ x,
                            const float* __restrict__ gw,  const float* __restrict__ gb,
                            const float* __restrict__ thw, const float* __restrict__ thb,
                            const float* __restrict__ phw, const float* __restrict__ phb)
{
    __shared__ float xd[64][64];    // [c][p]
    __shared__ float Wm[48][64];    // rows 0..15 theta, 16..31 phi, 32..47 g
    __shared__ float Bm[48];

    int b  = blockIdx.x >> 6;
    int oi = blockIdx.x & 63;
    int t  = threadIdx.x;  // 256

    for (int idx = t; idx < 16 * 64; idx += 256) {
        Wm[idx >> 6][idx & 63]        = thw[idx];
        Wm[16 + (idx >> 6)][idx & 63] = phw[idx];
        Wm[32 + (idx >> 6)][idx & 63] = gw[idx];
    }
    if (t < 16) { Bm[t] = thb[t]; Bm[16 + t] = phb[t]; Bm[32 + t] = gb[t]; }

    for (int idx = t; idx < 4096; idx += 256) {
        int c = idx >> 6, oj = idx & 63;
        xd[c][oj] = x[(((size_t)b * C + c) * H + 2 * oi + 1) * W + 2 * oj + 1];
    }
    __syncthreads();

    int base_n = b * N + oi * 64;
    for (int idx = t; idx < 3072; idx += 256) {
        int p = idx & 63, o = idx >> 6;   // o in 0..47
        float s0 = 0.f, s1 = 0.f, s2 = 0.f, s3 = 0.f;
        #pragma unroll
        for (int c = 0; c < 64; c += 4) {
            s0 += Wm[o][c]     * xd[c][p];
            s1 += Wm[o][c + 1] * xd[c + 1][p];
            s2 += Wm[o][c + 2] * xd[c + 2][p];
            s3 += Wm[o][c + 3] * xd[c + 3][p];
        }
        float s = Bm[o] + ((s0 + s1) + (s2 + s3));
        int which = o >> 4, oo = o & 15;
        g_qkv[((size_t)which * (B * N) + (base_n + p)) * IC + oo] = s;
    }
}

// ------------------- K2: flash attention (no-max online softmax, split-K=4, packed f32x2) -------------------
#define TK 128
#define KPC (N / SPLITK)   // keys per CTA = 1024
__global__ void __launch_bounds__(128, 4) k_attn()   // 128 regs/thread -> NO spills
{
    __shared__ ulonglong2 Ks[TK * 4];   // row j at [j*4..j*4+3], each 16B = 2 packed pairs
    __shared__ ulonglong2 Vs[TK * 4];

    int cta  = blockIdx.x;              // 0..511
    int b    = cta >> 7;
    int rest = cta & 127;
    int qt   = rest >> 2;               // 0..31 query tile
    int part = rest & 3;                // split-K quarter
    int t    = threadIdx.x;             // 128

    int n = b * N + qt * 128 + t;       // this thread's query

    const float* Q = g_qkv;
    const float* K = g_qkv + (size_t)(B * N) * IC;
    const float* V = g_qkv + (size_t)2 * (B * N) * IC;

    u64 q[8];
    {
        const u64* qv = (const u64*)(Q + (size_t)n * IC);
        #pragma unroll
        for (int i = 0; i < 8; i++) q[i] = qv[i];
    }

    u64 o[8];
    #pragma unroll
    for (int i = 0; i < 8; i++) o[i] = 0ull;
    float l = 0.f;

    int kbase = b * N + part * KPC;
    for (int tile = 0; tile < KPC; tile += TK) {
        const ulonglong2* Kg = (const ulonglong2*)(K + (size_t)(kbase + tile) * IC);
        const ulonglong2* Vg = (const ulonglong2*)(V + (size_t)(kbase + tile) * IC);
        #pragma unroll
        for (int i = t; i < TK * 4; i += 128) { Ks[i] = Kg[i]; Vs[i] = Vg[i]; }
        __syncthreads();

        #pragma unroll 4
        for (int kk = 0; kk < TK; kk++) {
            ulonglong2 ka = Ks[kk * 4 + 0], kb = Ks[kk * 4 + 1];
            ulonglong2 kc = Ks[kk * 4 + 2], kd = Ks[kk * 4 + 3];
            // two independent packed dot chains (depth 4)
            u64 sA = mul2(q[0], ka.x);
            u64 sB = mul2(q[1], ka.y);
            sA = fma2(q[2], kb.x, sA);
            sB = fma2(q[3], kb.y, sB);
            sA = fma2(q[4], kc.x, sA);
            sB = fma2(q[5], kc.y, sB);
            sA = fma2(q[6], kd.x, sA);
            sB = fma2(q[7], kd.y, sB);
            u64 sP = add2(sA, sB);
            float lo, hi;
            asm("mov.b64 {%0,%1},%2;" : "=f"(lo), "=f"(hi) : "l"(sP));
            float p = __expf(lo + hi);
            l += p;
            u64 p2;
            asm("mov.b64 %0,{%1,%1};" : "=l"(p2) : "f"(p));
            ulonglong2 va = Vs[kk * 4 + 0], vb = Vs[kk * 4 + 1];
            ulonglong2 vc = Vs[kk * 4 + 2], vd = Vs[kk * 4 + 3];
            o[0] = fma2(p2, va.x, o[0]);
            o[1] = fma2(p2, va.y, o[1]);
            o[2] = fma2(p2, vb.x, o[2]);
            o[3] = fma2(p2, vb.y, o[3]);
            o[4] = fma2(p2, vc.x, o[4]);
            o[5] = fma2(p2, vc.y, o[5]);
            o[6] = fma2(p2, vd.x, o[6]);
            o[7] = fma2(p2, vd.y, o[7]);
        }
        __syncthreads();
    }

    ulonglong2* O = (ulonglong2*)(g_opart + ((size_t)part * (B * N) + n) * IC);
    O[0] = make_ulonglong2(o[0], o[1]);
    O[1] = make_ulonglong2(o[2], o[3]);
    O[2] = make_ulonglong2(o[4], o[5]);
    O[3] = make_ulonglong2(o[6], o[7]);
    g_lpart[(size_t)part * (B * N) + n] = l;
}

// ------------------- K2b: merge split-K partials -------------------
__global__ void k_merge()
{
    int n = blockIdx.x * 256 + threadIdx.x;   // 0..16383
    if (n >= B * N) return;
    float l = 0.f;
    #pragma unroll
    for (int p = 0; p < SPLITK; p++) l += g_lpart[(size_t)p * (B * N) + n];
    float inv = 1.f / l;
    float acc[16];
    #pragma unroll
    for (int i = 0; i < 16; i++) acc[i] = 0.f;
    #pragma unroll
    for (int p = 0; p < SPLITK; p++) {
        const float4* a = (const float4*)(g_opart + ((size_t)p * (B * N) + n) * IC);
        #pragma unroll
        for (int i = 0; i < 4; i++) {
            float4 v = a[i];
            acc[i * 4 + 0] += v.x; acc[i * 4 + 1] += v.y;
            acc[i * 4 + 2] += v.z; acc[i * 4 + 3] += v.w;
        }
    }
    float4* y = (float4*)(g_y + (size_t)n * IC);
    #pragma unroll
    for (int i = 0; i < 4; i++) {
        float4 r;
        r.x = acc[i * 4 + 0] * inv; r.y = acc[i * 4 + 1] * inv;
        r.z = acc[i * 4 + 2] * inv; r.w = acc[i * 4 + 3] * inv;
        y[i] = r;
    }
}

// ------------------- K3: upsample + out conv + residual (no BN here) -------------------
// jax scale_and_translate, scale=2, trans=+0.5  =>  sample_f = 0.5*o - 0.5 (clamped taps)
__global__ void k_out(const float* __restrict__ x,
                      const float* __restrict__ ow, const float* __restrict__ ob)
{
    __shared__ float yr[16][64];      // vertically interpolated row
    __shared__ float yup[16][128];    // fully interpolated row
    __shared__ float Wo[64][16];

    int b = blockIdx.x >> 7;
    int h = blockIdx.x & 127;
    int t = threadIdx.x;  // 256

    for (int idx = t; idx < 1024; idx += 256) Wo[idx >> 4][idx & 15] = ow[idx];

    float fh = 0.5f * (float)h - 0.5f;
    int   ihf = (int)floorf(fh);
    float w1  = fh - (float)ihf;
    int ih0 = ihf < 0 ? 0 : ihf;
    int ih1 = (ihf + 1) > 63 ? 63 : (ihf + 1);

    for (int idx = t; idx < 1024; idx += 256) {
        int i = idx >> 6, jw = idx & 63;
        float a = g_y[((size_t)b * N + ih0 * 64 + jw) * IC + i];
        float c = g_y[((size_t)b * N + ih1 * 64 + jw) * IC + i];
        yr[i][jw] = (1.f - w1) * a + w1 * c;
    }
    __syncthreads();

    for (int idx = t; idx < 2048; idx += 256) {
        int i = idx >> 7, w = idx & 127;
        float fw = 0.5f * (float)w - 0.5f;
        int   jf = (int)floorf(fw);
        float ww = fw - (float)jf;
        int j0 = jf < 0 ? 0 : jf;
        int j1 = (jf + 1) > 63 ? 63 : (jf + 1);
        yup[i][w] = (1.f - ww) * yr[i][j0] + ww * yr[i][j1];
    }
    __syncthreads();

    int c2 = t >> 7;          // 0: even channels, 1: odd
    int w  = t & 127;

    const float* xrow = x   + ((size_t)b * C * H + h) * W;
    float*       zrow = g_z + ((size_t)b * C * H + h) * W;

    for (int c = c2; c < C; c += 2) {
        float s = ob[c];
        #pragma unroll
        for (int i = 0; i < 16; i++) s += Wo[c][i] * yup[i][w];
        zrow[(size_t)c * (H * W) + w] = xrow[(size_t)c * (H * W) + w] + s;
    }
}

// ------------------- K3b: BN partial reduction over g_z (deterministic) -------------------
// grid = B*C*4 = 1024 CTAs, 256 threads; each CTA reduces 4096 contiguous floats
__global__ void k_bnred()
{
    __shared__ float ss[8], sq[8];
    int plane = blockIdx.x >> 2;       // b*64 + c, 0..255
    int chunk = blockIdx.x & 3;
    int t = threadIdx.x;

    const float4* p = (const float4*)(g_z + (size_t)plane * (H * W) + chunk * 4096);
    float s = 0.f, q = 0.f;
    #pragma unroll
    for (int i = 0; i < 4; i++) {
        float4 v = p[i * 256 + t];
        s += ((v.x + v.y) + (v.z + v.w));
        q += ((v.x * v.x + v.y * v.y) + (v.z * v.z + v.w * v.w));
    }
    #pragma unroll
    for (int off = 16; off; off >>= 1) {
        s += __shfl_down_sync(0xffffffffu, s, off);
        q += __shfl_down_sync(0xffffffffu, q, off);
    }
    int warp = t >> 5, lane = t & 31;
    if (lane == 0) { ss[warp] = s; sq[warp] = q; }
    __syncthreads();
    if (t == 0) {
        float S = ((ss[0] + ss[1]) + (ss[2] + ss[3])) + ((ss[4] + ss[5]) + (ss[6] + ss[7]));
        float Q = ((sq[0] + sq[1]) + (sq[2] + sq[3])) + ((sq[4] + sq[5]) + (sq[6] + sq[7]));
        g_bnpart[((size_t)plane * 4 + chunk) * 2 + 0] = S;
        g_bnpart[((size_t)plane * 4 + chunk) * 2 + 1] = Q;
    }
}

// ------------------- K4: finalize BN stats (deterministic fixed-order) -------------------
__global__ void k_stats()
{
    int c = threadIdx.x;   // 64 threads
    if (c >= C) return;
    float s = 0.f, q = 0.f;
    #pragma unroll
    for (int b = 0; b < B; b++)
        #pragma unroll
        for (int ch = 0; ch < 4; ch++) {
            size_t idx = (((size_t)b * C + c) * 4 + ch) * 2;
            s += g_bnpart[idx + 0];
            q += g_bnpart[idx + 1];
        }
    float mean = s * (1.f / (float)BN_COUNT);
    float var  = q * (1.f / (float)BN_COUNT) - mean * mean;
    g_bnstat[c * 2 + 0] = mean;
    g_bnstat[c * 2 + 1] = rsqrtf(var + 1e-5f);
}

// ------------------- K5: normalize -------------------
__global__ void k_norm(const float* __restrict__ gamma, const float* __restrict__ beta,
                       float* __restrict__ out)
{
    size_t i4 = (size_t)blockIdx.x * 256 + threadIdx.x;
    int c = (int)((i4 >> 12) & 63);
    float mean = g_bnstat[c * 2 + 0];
    float rstd = g_bnstat[c * 2 + 1];
    float ga = gamma[c] * rstd;
    float be = beta[c] - mean * ga;
    float4 z = ((const float4*)g_z)[i4];
    float4 r;
    r.x = z.x * ga + be; r.y = z.y * ga + be;
    r.z = z.z * ga + be; r.w = z.w * ga + be;
    ((float4*)out)[i4] = r;
}

// ------------------------------- launch -------------------------------
extern "C" void kernel_launch(void* const* d_in, const int* in_sizes, int n_in,
                              void* d_out, int out_size)
{
    const float* x     = (const float*)d_in[0];
    const float* g_w   = (const float*)d_in[1];
    const float* g_b   = (const float*)d_in[2];
    const float* th_w  = (const float*)d_in[3];
    const float* th_b  = (const float*)d_in[4];
    const float* ph_w  = (const float*)d_in[5];
    const float* ph_b  = (const float*)d_in[6];
    const float* out_w = (const float*)d_in[7];
    const float* out_b = (const float*)d_in[8];
    const float* gamma = (const float*)d_in[9];
    const float* beta  = (const float*)d_in[10];
    float* out = (float*)d_out;

    k_down_proj<<<B * 64, 256>>>(x, g_w, g_b, th_w, th_b, ph_w, ph_b);
    k_attn<<<B * 32 * SPLITK, 128>>>();
    k_merge<<<64, 256>>>();
    k_out<<<B * H, 256>>>(x, out_w, out_b);
    k_bnred<<<B * C * 4, 256>>>();
    k_stats<<<1, 64>>>();
    k_norm<<<4096, 256>>>(gamma, beta, out);
}

// round 7
// speedup vs baseline: 2.1087x; 2.1087x over previous
#include <cuda_runtime.h>
#include <math.h>

// Problem constants
#define B 4
#define C 64
#define IC 16
#define H 128
#define W 128
#define DH 64
#define DW 64
#define N 4096          // DH*DW
#define BN_COUNT (B*H*W)
#define SPLITK 4
#define LOG2E 1.44269504088896340736f

// ------------------------- scratch (static device) -------------------------
__device__ float g_qkv[3 * B * N * IC];            // 0=Q(theta, pre-scaled by log2e) 1=K(phi) 2=V(g)
__device__ float g_opart[SPLITK * B * N * IC];
__device__ float g_lpart[SPLITK * B * N];
__device__ float g_y[B * N * IC];
__device__ float g_z[B * C * H * W];
__device__ float g_bnpart[B * C * 4 * 2];
__device__ float g_bnstat[C * 2];

// ---- small helpers ----
__device__ __forceinline__ unsigned cvt_tf32(float f) {
    unsigned u; asm("cvt.rna.tf32.f32 %0,%1;" : "=r"(u) : "f"(f)); return u;
}
__device__ __forceinline__ float ex2a(float f) {
    float r; asm("ex2.approx.ftz.f32 %0,%1;" : "=f"(r) : "f"(f)); return r;
}
__device__ __forceinline__ void mma_tf32(float* d, const unsigned* a, unsigned b0, unsigned b1) {
    asm("mma.sync.aligned.m16n8k8.row.col.f32.tf32.tf32.f32 "
        "{%0,%1,%2,%3},{%4,%5,%6,%7},{%8,%9},{%0,%1,%2,%3};"
        : "+f"(d[0]), "+f"(d[1]), "+f"(d[2]), "+f"(d[3])
        : "r"(a[0]), "r"(a[1]), "r"(a[2]), "r"(a[3]), "r"(b0), "r"(b1));
}

// ------------------- K1: downsample (odd-pixel subsample) + QKV projections -------------------
// jax scale_and_translate, scale=0.5, trans=-0.25 => sample_f = 2*o+1 (exact hit)
// theta output is pre-scaled by log2e so attention can use ex2 directly.
__global__ void k_down_proj(const float* __restrict__ x,
                            const float* __restrict__ gw,  const float* __restrict__ gb,
                            const float* __restrict__ thw, const float* __restrict__ thb,
                            const float* __restrict__ phw, const float* __restrict__ phb)
{
    __shared__ float xd[64][64];
    __shared__ float Wm[48][64];
    __shared__ float Bm[48];

    int b  = blockIdx.x >> 6;
    int oi = blockIdx.x & 63;
    int t  = threadIdx.x;  // 256

    for (int idx = t; idx < 16 * 64; idx += 256) {
        Wm[idx >> 6][idx & 63]        = thw[idx] * LOG2E;   // theta scaled
        Wm[16 + (idx >> 6)][idx & 63] = phw[idx];
        Wm[32 + (idx >> 6)][idx & 63] = gw[idx];
    }
    if (t < 16) { Bm[t] = thb[t] * LOG2E; Bm[16 + t] = phb[t]; Bm[32 + t] = gb[t]; }

    for (int idx = t; idx < 4096; idx += 256) {
        int c = idx >> 6, oj = idx & 63;
        xd[c][oj] = x[(((size_t)b * C + c) * H + 2 * oi + 1) * W + 2 * oj + 1];
    }
    __syncthreads();

    int base_n = b * N + oi * 64;
    for (int idx = t; idx < 3072; idx += 256) {
        int p = idx & 63, o = idx >> 6;
        float s0 = 0.f, s1 = 0.f, s2 = 0.f, s3 = 0.f;
        #pragma unroll
        for (int c = 0; c < 64; c += 4) {
            s0 += Wm[o][c]     * xd[c][p];
            s1 += Wm[o][c + 1] * xd[c + 1][p];
            s2 += Wm[o][c + 2] * xd[c + 2][p];
            s3 += Wm[o][c + 3] * xd[c + 3][p];
        }
        float s = Bm[o] + ((s0 + s1) + (s2 + s3));
        int which = o >> 4, oo = o & 15;
        g_qkv[((size_t)which * (B * N) + (base_n + p)) * IC + oo] = s;
    }
}

// ------------------- K2: tf32 mma flash attention (no-max softmax, split-K=4) -------------------
// CTA: 128 threads = 4 warps. Warp owns 16 queries; CTA q-tile = 64.
// Key tiles of 32 in smem. grid = B * 64 * SPLITK = 1024.
#define KT 32
#define KPC (N / SPLITK)   // 1024 keys per CTA
__global__ void __launch_bounds__(128, 4) k_attn()
{
    __shared__ float Ks[KT][20];   // [key][d], pad 20 -> conflict-free B-frag loads
    __shared__ float Vt[IC][36];   // [d][key], pad 36 -> conflict-free B-frag loads

    int b    = blockIdx.x >> 8;
    int qt   = (blockIdx.x >> 2) & 63;
    int part = blockIdx.x & 3;
    int t    = threadIdx.x;
    int w    = t >> 5;
    int lane = t & 31;
    int g    = lane >> 2;      // groupID 0..7
    int t4   = lane & 3;       // threadID in group

    const float* Q = g_qkv;
    const float* K = g_qkv + (size_t)(B * N) * IC;
    const float* V = g_qkv + (size_t)2 * (B * N) * IC;

    int q0 = b * N + qt * 64 + w * 16;   // warp's first query (global row)

    // Q A-fragments (2 k-steps over d=16), tf32
    unsigned qa[2][4];
    #pragma unroll
    for (int s = 0; s < 2; s++) {
        qa[s][0] = cvt_tf32(Q[(size_t)(q0 + g)     * IC + s * 8 + t4]);
        qa[s][1] = cvt_tf32(Q[(size_t)(q0 + g + 8) * IC + s * 8 + t4]);
        qa[s][2] = cvt_tf32(Q[(size_t)(q0 + g)     * IC + s * 8 + t4 + 4]);
        qa[s][3] = cvt_tf32(Q[(size_t)(q0 + g + 8) * IC + s * 8 + t4 + 4]);
    }

    float od[2][4];            // PV accum: n-chunks over d (2 x 8)
    #pragma unroll
    for (int c = 0; c < 2; c++)
        #pragma unroll
        for (int i = 0; i < 4; i++) od[c][i] = 0.f;
    float l0 = 0.f, l1 = 0.f;  // row sums for rows g and g+8 (this thread's cols)

    int kbase = b * N + part * KPC;
    for (int kt = 0; kt < KPC; kt += KT) {
        // load K tile (32x16) and V tile transposed (16x32)
        {
            int key = t >> 2, d4 = (t & 3) * 4;
            float4 kv = *(const float4*)(K + (size_t)(kbase + kt + key) * IC + d4);
            *(float4*)&Ks[key][d4] = kv;
            float4 vv = *(const float4*)(V + (size_t)(kbase + kt + key) * IC + d4);
            Vt[d4 + 0][key] = vv.x; Vt[d4 + 1][key] = vv.y;
            Vt[d4 + 2][key] = vv.z; Vt[d4 + 3][key] = vv.w;
        }
        __syncthreads();

        // S = Q K^T : 4 key-chunks of 8, 2 k-steps over d
        float p[4][4];
        #pragma unroll
        for (int c = 0; c < 4; c++) {
            float sc[4] = {0.f, 0.f, 0.f, 0.f};
            #pragma unroll
            for (int s = 0; s < 2; s++) {
                unsigned b0 = cvt_tf32(Ks[c * 8 + g][s * 8 + t4]);
                unsigned b1 = cvt_tf32(Ks[c * 8 + g][s * 8 + t4 + 4]);
                mma_tf32(sc, qa[s], b0, b1);
            }
            // exp2 (theta pre-scaled by log2e) + l partials
            p[c][0] = ex2a(sc[0]); p[c][1] = ex2a(sc[1]);
            p[c][2] = ex2a(sc[2]); p[c][3] = ex2a(sc[3]);
            l0 += p[c][0] + p[c][1];
            l1 += p[c][2] + p[c][3];
        }

        // PV: D(16q x 16d) += P(16x32) V(32x16). 4 k-steps over keys, 2 n-chunks over d.
        int srcA = (lane & ~3) | (t4 >> 1);
        int srcB = srcA + 2;
        bool odd = (t4 & 1);
        #pragma unroll
        for (int s = 0; s < 4; s++) {
            // convert C-frag p[s][*] (cols 2t4,2t4+1) to A-frag (cols t4, t4+4)
            float e00 = __shfl_sync(0xffffffffu, p[s][0], srcA);
            float e01 = __shfl_sync(0xffffffffu, p[s][1], srcA);
            float e10 = __shfl_sync(0xffffffffu, p[s][0], srcB);
            float e11 = __shfl_sync(0xffffffffu, p[s][1], srcB);
            float e20 = __shfl_sync(0xffffffffu, p[s][2], srcA);
            float e21 = __shfl_sync(0xffffffffu, p[s][3], srcA);
            float e30 = __shfl_sync(0xffffffffu, p[s][2], srcB);
            float e31 = __shfl_sync(0xffffffffu, p[s][3], srcB);
            unsigned pa[4];
            pa[0] = cvt_tf32(odd ? e01 : e00);   // (g,    t4)
            pa[1] = cvt_tf32(odd ? e21 : e20);   // (g+8,  t4)
            pa[2] = cvt_tf32(odd ? e11 : e10);   // (g,    t4+4)
            pa[3] = cvt_tf32(odd ? e31 : e30);   // (g+8,  t4+4)
            #pragma unroll
            for (int c = 0; c < 2; c++) {
                unsigned vb0 = cvt_tf32(Vt[c * 8 + g][s * 8 + t4]);
                unsigned vb1 = cvt_tf32(Vt[c * 8 + g][s * 8 + t4 + 4]);
                mma_tf32(od[c], pa, vb0, vb1);
            }
        }
        __syncthreads();
    }

    // reduce l across the 4 lanes of each row group
    l0 += __shfl_xor_sync(0xffffffffu, l0, 1);
    l0 += __shfl_xor_sync(0xffffffffu, l0, 2);
    l1 += __shfl_xor_sync(0xffffffffu, l1, 1);
    l1 += __shfl_xor_sync(0xffffffffu, l1, 2);
    if (t4 == 0) {
        g_lpart[(size_t)part * (B * N) + q0 + g]     = l0;
        g_lpart[(size_t)part * (B * N) + q0 + g + 8] = l1;
    }

    // store O partials: rows g (regs 0,1) / g+8 (regs 2,3), cols c*8 + 2t4, +1
    float* Ob = g_opart + (size_t)part * (B * N) * IC;
    #pragma unroll
    for (int c = 0; c < 2; c++) {
        *(float2*)&Ob[(size_t)(q0 + g)     * IC + c * 8 + 2 * t4] = make_float2(od[c][0], od[c][1]);
        *(float2*)&Ob[(size_t)(q0 + g + 8) * IC + c * 8 + 2 * t4] = make_float2(od[c][2], od[c][3]);
    }
}

// ------------------- K2b: merge split-K partials -------------------
__global__ void k_merge()
{
    int n = blockIdx.x * 256 + threadIdx.x;
    if (n >= B * N) return;
    float l = 0.f;
    #pragma unroll
    for (int p = 0; p < SPLITK; p++) l += g_lpart[(size_t)p * (B * N) + n];
    float inv = 1.f / l;
    float acc[16];
    #pragma unroll
    for (int i = 0; i < 16; i++) acc[i] = 0.f;
    #pragma unroll
    for (int p = 0; p < SPLITK; p++) {
        const float4* a = (const float4*)(g_opart + ((size_t)p * (B * N) + n) * IC);
        #pragma unroll
        for (int i = 0; i < 4; i++) {
            float4 v = a[i];
            acc[i * 4 + 0] += v.x; acc[i * 4 + 1] += v.y;
            acc[i * 4 + 2] += v.z; acc[i * 4 + 3] += v.w;
        }
    }
    float4* y = (float4*)(g_y + (size_t)n * IC);
    #pragma unroll
    for (int i = 0; i < 4; i++) {
        float4 r;
        r.x = acc[i * 4 + 0] * inv; r.y = acc[i * 4 + 1] * inv;
        r.z = acc[i * 4 + 2] * inv; r.w = acc[i * 4 + 3] * inv;
        y[i] = r;
    }
}

// ------------------- K3: upsample + out conv + residual -------------------
// jax scale_and_translate, scale=2, trans=+0.5 => sample_f = 0.5*o - 0.5 (clamped taps)
__global__ void k_out(const float* __restrict__ x,
                      const float* __restrict__ ow, const float* __restrict__ ob)
{
    __shared__ float yr[16][64];
    __shared__ float yup[16][128];
    __shared__ float Wo[64][16];

    int b = blockIdx.x >> 7;
    int h = blockIdx.x & 127;
    int t = threadIdx.x;  // 256

    for (int idx = t; idx < 1024; idx += 256) Wo[idx >> 4][idx & 15] = ow[idx];

    float fh = 0.5f * (float)h - 0.5f;
    int   ihf = (int)floorf(fh);
    float w1  = fh - (float)ihf;
    int ih0 = ihf < 0 ? 0 : ihf;
    int ih1 = (ihf + 1) > 63 ? 63 : (ihf + 1);

    for (int idx = t; idx < 1024; idx += 256) {
        int i = idx >> 6, jw = idx & 63;
        float a = g_y[((size_t)b * N + ih0 * 64 + jw) * IC + i];
        float c = g_y[((size_t)b * N + ih1 * 64 + jw) * IC + i];
        yr[i][jw] = (1.f - w1) * a + w1 * c;
    }
    __syncthreads();

    for (int idx = t; idx < 2048; idx += 256) {
        int i = idx >> 7, w = idx & 127;
        float fw = 0.5f * (float)w - 0.5f;
        int   jf = (int)floorf(fw);
        float ww = fw - (float)jf;
        int j0 = jf < 0 ? 0 : jf;
        int j1 = (jf + 1) > 63 ? 63 : (jf + 1);
        yup[i][w] = (1.f - ww) * yr[i][j0] + ww * yr[i][j1];
    }
    __syncthreads();

    int c2 = t >> 7;
    int w  = t & 127;

    const float* xrow = x   + ((size_t)b * C * H + h) * W;
    float*       zrow = g_z + ((size_t)b * C * H + h) * W;

    for (int c = c2; c < C; c += 2) {
        float s = ob[c];
        #pragma unroll
        for (int i = 0; i < 16; i++) s += Wo[c][i] * yup[i][w];
        zrow[(size_t)c * (H * W) + w] = xrow[(size_t)c * (H * W) + w] + s;
    }
}

// ------------------- K3b: BN partial reduction over g_z (deterministic) -------------------
__global__ void k_bnred()
{
    __shared__ float ss[8], sq[8];
    int plane = blockIdx.x >> 2;
    int chunk = blockIdx.x & 3;
    int t = threadIdx.x;

    const float4* p = (const float4*)(g_z + (size_t)plane * (H * W) + chunk * 4096);
    float s = 0.f, q = 0.f;
    #pragma unroll
    for (int i = 0; i < 4; i++) {
        float4 v = p[i * 256 + t];
        s += ((v.x + v.y) + (v.z + v.w));
        q += ((v.x * v.x + v.y * v.y) + (v.z * v.z + v.w * v.w));
    }
    #pragma unroll
    for (int off = 16; off; off >>= 1) {
        s += __shfl_down_sync(0xffffffffu, s, off);
        q += __shfl_down_sync(0xffffffffu, q, off);
    }
    int warp = t >> 5, lane = t & 31;
    if (lane == 0) { ss[warp] = s; sq[warp] = q; }
    __syncthreads();
    if (t == 0) {
        float S = ((ss[0] + ss[1]) + (ss[2] + ss[3])) + ((ss[4] + ss[5]) + (ss[6] + ss[7]));
        float Q = ((sq[0] + sq[1]) + (sq[2] + sq[3])) + ((sq[4] + sq[5]) + (sq[6] + sq[7]));
        g_bnpart[((size_t)plane * 4 + chunk) * 2 + 0] = S;
        g_bnpart[((size_t)plane * 4 + chunk) * 2 + 1] = Q;
    }
}

// ------------------- K4: finalize BN stats -------------------
__global__ void k_stats()
{
    int c = threadIdx.x;
    if (c >= C) return;
    float s = 0.f, q = 0.f;
    #pragma unroll
    for (int b = 0; b < B; b++)
        #pragma unroll
        for (int ch = 0; ch < 4; ch++) {
            size_t idx = (((size_t)b * C + c) * 4 + ch) * 2;
            s += g_bnpart[idx + 0];
            q += g_bnpart[idx + 1];
        }
    float mean = s * (1.f / (float)BN_COUNT);
    float var  = q * (1.f / (float)BN_COUNT) - mean * mean;
    g_bnstat[c * 2 + 0] = mean;
    g_bnstat[c * 2 + 1] = rsqrtf(var + 1e-5f);
}

// ------------------- K5: normalize -------------------
__global__ void k_norm(const float* __restrict__ gamma, const float* __restrict__ beta,
                       float* __restrict__ out)
{
    size_t i4 = (size_t)blockIdx.x * 256 + threadIdx.x;
    int c = (int)((i4 >> 12) & 63);
    float mean = g_bnstat[c * 2 + 0];
    float rstd = g_bnstat[c * 2 + 1];
    float ga = gamma[c] * rstd;
    float be = beta[c] - mean * ga;
    float4 z = ((const float4*)g_z)[i4];
    float4 r;
    r.x = z.x * ga + be; r.y = z.y * ga + be;
    r.z = z.z * ga + be; r.w = z.w * ga + be;
    ((float4*)out)[i4] = r;
}

// ------------------------------- launch -------------------------------
extern "C" void kernel_launch(void* const* d_in, const int* in_sizes, int n_in,
                              void* d_out, int out_size)
{
    const float* x     = (const float*)d_in[0];
    const float* g_w   = (const float*)d_in[1];
    const float* g_b   = (const float*)d_in[2];
    const float* th_w  = (const float*)d_in[3];
    const float* th_b  = (const float*)d_in[4];
    const float* ph_w  = (const float*)d_in[5];
    const float* ph_b  = (const float*)d_in[6];
    const float* out_w = (const float*)d_in[7];
    const float* out_b = (const float*)d_in[8];
    const float* gamma = (const float*)d_in[9];
    const float* beta  = (const float*)d_in[10];
    float* out = (float*)d_out;

    k_down_proj<<<B * 64, 256>>>(x, g_w, g_b, th_w, th_b, ph_w, ph_b);
    k_attn<<<B * 64 * SPLITK, 128>>>();
    k_merge<<<64, 256>>>();
    k_out<<<B * H, 256>>>(x, out_w, out_b);
    k_bnred<<<B * C * 4, 256>>>();
    k_stats<<<1, 64>>>();
    k_norm<<<4096, 256>>>(gamma, beta, out);
}

// round 8
// speedup vs baseline: 3.0351x; 1.4393x over previous
#include <cuda_runtime.h>
#include <cuda_fp16.h>
#include <math.h>

#define B 4
#define C 64
#define IC 16
#define H 128
#define W 128
#define N 4096
#define BN_COUNT (B*H*W)
#define SPLITK 4
#define LOG2E 1.44269504088896340736f

// ------------------------- scratch -------------------------
__device__ __half g_qh[B * N * IC];        // Q (theta * log2e)  [n][d]
__device__ __half g_kh[B * N * IC];        // K (phi)            [n][d]
__device__ __half g_vth[B * IC * N];       // V transposed       [b][d][n]
__device__ float g_opart[SPLITK * B * N * IC];
__device__ float g_lpart[SPLITK * B * N];
__device__ float g_mpart[SPLITK * B * N];
__device__ float g_y[B * N * IC];
__device__ float g_z[B * C * H * W];
__device__ float g_bnpart[B * C * 4 * 2];
__device__ float g_bnstat[C * 2];

__device__ __forceinline__ float ex2a(float f) {
    float r; asm("ex2.approx.ftz.f32 %0,%1;" : "=f"(r) : "f"(f)); return r;
}
__device__ __forceinline__ unsigned pack2(float a, float b) {
    __half2 h = __floats2half2_rn(a, b);
    return *(unsigned*)&h;
}
__device__ __forceinline__ void mma_f16(float* d, unsigned a0, unsigned a1, unsigned a2, unsigned a3,
                                        unsigned b0, unsigned b1) {
    asm("mma.sync.aligned.m16n8k16.row.col.f32.f16.f16.f32 "
        "{%0,%1,%2,%3},{%4,%5,%6,%7},{%8,%9},{%0,%1,%2,%3};"
        : "+f"(d[0]), "+f"(d[1]), "+f"(d[2]), "+f"(d[3])
        : "r"(a0), "r"(a1), "r"(a2), "r"(a3), "r"(b0), "r"(b1));
}

// ------------------- K1: downsample (odd-pixel subsample) + QKV (fp16 out) -------------------
// jax scale_and_translate, scale=0.5, trans=-0.25 => sample_f = 2*o+1 (exact hit)
__global__ void __launch_bounds__(256) k_down_proj(
    const float* __restrict__ x,
    const float* __restrict__ gw,  const float* __restrict__ gb,
    const float* __restrict__ thw, const float* __restrict__ thb,
    const float* __restrict__ phw, const float* __restrict__ phb)
{
    __shared__ float xd[64][68];     // [p][c] padded
    __shared__ float Wm[48][64];     // 0-15 theta*log2e, 16-31 phi, 32-47 g
    __shared__ float Bm[48];
    __shared__ __half qks[2][64][16];

    int b  = blockIdx.x >> 6;
    int oi = blockIdx.x & 63;
    int t  = threadIdx.x;  // 256

    for (int idx = t; idx < 16 * 64; idx += 256) {
        Wm[idx >> 6][idx & 63]        = thw[idx] * LOG2E;
        Wm[16 + (idx >> 6)][idx & 63] = phw[idx];
        Wm[32 + (idx >> 6)][idx & 63] = gw[idx];
    }
    if (t < 16) { Bm[t] = thb[t] * LOG2E; Bm[16 + t] = phb[t]; Bm[32 + t] = gb[t]; }

    for (int idx = t; idx < 4096; idx += 256) {
        int c = idx >> 6, p = idx & 63;
        xd[p][c] = x[(((size_t)b * C + c) * H + 2 * oi + 1) * W + 2 * p + 1];
    }
    __syncthreads();

    int p   = t & 63;
    int grp = t >> 6;    // outputs grp*12 .. grp*12+11

    float xv[64];
    #pragma unroll
    for (int k = 0; k < 16; k++) *(float4*)&xv[4 * k] = *(float4*)&xd[p][4 * k];

    int base_n = b * N + oi * 64;
    #pragma unroll
    for (int j = 0; j < 12; j++) {
        int o = grp * 12 + j;
        float s0 = 0.f, s1 = 0.f, s2 = 0.f, s3 = 0.f;
        #pragma unroll
        for (int k = 0; k < 16; k++) {
            float4 wv = *(float4*)&Wm[o][4 * k];
            s0 += wv.x * xv[4 * k];
            s1 += wv.y * xv[4 * k + 1];
            s2 += wv.z * xv[4 * k + 2];
            s3 += wv.w * xv[4 * k + 3];
        }
        float s = Bm[o] + ((s0 + s1) + (s2 + s3));
        int which = o >> 4, oo = o & 15;
        if (which < 2) qks[which][p][oo] = __float2half_rn(s);
        else           g_vth[((size_t)b * IC + oo) * N + oi * 64 + p] = __float2half_rn(s);
    }
    __syncthreads();

    // coalesced Q/K stores
    for (int idx = t; idx < 1024; idx += 256) {
        int which = idx >> 9;
        int rest  = idx & 511;
        int pp = rest >> 3, u = rest & 7;
        unsigned v = *(unsigned*)&qks[which][pp][u * 2];
        __half* dst = which ? g_kh : g_qh;
        *((unsigned*)dst + (size_t)(base_n + pp) * 8 + u) = v;
    }
}

// ------------------- K2: fp16 mma flash attention, online max, split-K=4 -------------------
#define KT 32
#define KPC (N / SPLITK)
__global__ void __launch_bounds__(128) k_attn()
{
    __shared__ __half Ks[KT][24];    // [key][d], pad 24 halves (48B) -> conflict-free
    __shared__ __half Vt[IC][40];    // [d][key], pad 40 halves (80B) -> conflict-free

    int b    = blockIdx.x >> 8;
    int qt   = (blockIdx.x >> 2) & 63;
    int part = blockIdx.x & 3;
    int t    = threadIdx.x;
    int wp   = t >> 5;
    int lane = t & 31;
    int g    = lane >> 2;
    int t4   = lane & 3;

    int q0 = b * N + qt * 64 + wp * 16;

    unsigned qa0 = *(const unsigned*)(g_qh + (size_t)(q0 + g)     * IC + 2 * t4);
    unsigned qa1 = *(const unsigned*)(g_qh + (size_t)(q0 + g + 8) * IC + 2 * t4);
    unsigned qa2 = *(const unsigned*)(g_qh + (size_t)(q0 + g)     * IC + 2 * t4 + 8);
    unsigned qa3 = *(const unsigned*)(g_qh + (size_t)(q0 + g + 8) * IC + 2 * t4 + 8);

    float od[2][4];
    #pragma unroll
    for (int c = 0; c < 2; c++)
        #pragma unroll
        for (int i = 0; i < 4; i++) od[c][i] = 0.f;
    float m0 = -1e30f, m1 = -1e30f, l0 = 0.f, l1 = 0.f;

    int koff = part * KPC;    // within-batch key offset
    for (int kt = 0; kt < KPC; kt += KT) {
        {
            int key = t >> 2, seg = t & 3;
            *(uint2*)&Ks[key][seg * 4] =
                *(const uint2*)(g_kh + ((size_t)(b * N + koff + kt) + key) * IC + seg * 4);
            int d = t >> 3, seg8 = t & 7;
            *(uint2*)&Vt[d][seg8 * 4] =
                *(const uint2*)(g_vth + ((size_t)b * IC + d) * N + koff + kt + seg8 * 4);
        }
        __syncthreads();

        // S = Q K^T (4 key-chunks of 8)
        float p[4][4];
        #pragma unroll
        for (int c = 0; c < 4; c++) {
            float sc[4] = {0.f, 0.f, 0.f, 0.f};
            unsigned kb0 = *(const unsigned*)&Ks[c * 8 + g][2 * t4];
            unsigned kb1 = *(const unsigned*)&Ks[c * 8 + g][2 * t4 + 8];
            mma_f16(sc, qa0, qa1, qa2, qa3, kb0, kb1);
            p[c][0] = sc[0]; p[c][1] = sc[1]; p[c][2] = sc[2]; p[c][3] = sc[3];
        }

        // online max (log2 domain)
        float tm0 = fmaxf(fmaxf(fmaxf(p[0][0], p[0][1]), fmaxf(p[1][0], p[1][1])),
                          fmaxf(fmaxf(p[2][0], p[2][1]), fmaxf(p[3][0], p[3][1])));
        float tm1 = fmaxf(fmaxf(fmaxf(p[0][2], p[0][3]), fmaxf(p[1][2], p[1][3])),
                          fmaxf(fmaxf(p[2][2], p[2][3]), fmaxf(p[3][2], p[3][3])));
        tm0 = fmaxf(tm0, __shfl_xor_sync(0xffffffffu, tm0, 1));
        tm0 = fmaxf(tm0, __shfl_xor_sync(0xffffffffu, tm0, 2));
        tm1 = fmaxf(tm1, __shfl_xor_sync(0xffffffffu, tm1, 1));
        tm1 = fmaxf(tm1, __shfl_xor_sync(0xffffffffu, tm1, 2));
        float mn0 = fmaxf(m0, tm0), mn1 = fmaxf(m1, tm1);
        float f0 = ex2a(m0 - mn0), f1 = ex2a(m1 - mn1);
        m0 = mn0; m1 = mn1;
        l0 *= f0; l1 *= f1;
        od[0][0] *= f0; od[0][1] *= f0; od[1][0] *= f0; od[1][1] *= f0;
        od[0][2] *= f1; od[0][3] *= f1; od[1][2] *= f1; od[1][3] *= f1;

        #pragma unroll
        for (int c = 0; c < 4; c++) {
            p[c][0] = ex2a(p[c][0] - m0); p[c][1] = ex2a(p[c][1] - m0);
            p[c][2] = ex2a(p[c][2] - m1); p[c][3] = ex2a(p[c][3] - m1);
            l0 += p[c][0] + p[c][1];
            l1 += p[c][2] + p[c][3];
        }

        // PV: C-frag of S == A-frag of PV (no shuffles)
        #pragma unroll
        for (int s = 0; s < 2; s++) {
            unsigned pa0 = pack2(p[2 * s][0],     p[2 * s][1]);
            unsigned pa1 = pack2(p[2 * s][2],     p[2 * s][3]);
            unsigned pa2 = pack2(p[2 * s + 1][0], p[2 * s + 1][1]);
            unsigned pa3 = pack2(p[2 * s + 1][2], p[2 * s + 1][3]);
            #pragma unroll
            for (int nc = 0; nc < 2; nc++) {
                unsigned vb0 = *(const unsigned*)&Vt[nc * 8 + g][s * 16 + 2 * t4];
                unsigned vb1 = *(const unsigned*)&Vt[nc * 8 + g][s * 16 + 2 * t4 + 8];
                mma_f16(od[nc], pa0, pa1, pa2, pa3, vb0, vb1);
            }
        }
        __syncthreads();
    }

    l0 += __shfl_xor_sync(0xffffffffu, l0, 1);
    l0 += __shfl_xor_sync(0xffffffffu, l0, 2);
    l1 += __shfl_xor_sync(0xffffffffu, l1, 1);
    l1 += __shfl_xor_sync(0xffffffffu, l1, 2);
    if (t4 == 0) {
        size_t base = (size_t)part * (B * N);
        g_lpart[base + q0 + g]     = l0;
        g_lpart[base + q0 + g + 8] = l1;
        g_mpart[base + q0 + g]     = m0;
        g_mpart[base + q0 + g + 8] = m1;
    }

    float* Ob = g_opart + (size_t)part * (B * N) * IC;
    #pragma unroll
    for (int nc = 0; nc < 2; nc++) {
        *(float2*)&Ob[(size_t)(q0 + g)     * IC + nc * 8 + 2 * t4] = make_float2(od[nc][0], od[nc][1]);
        *(float2*)&Ob[(size_t)(q0 + g + 8) * IC + nc * 8 + 2 * t4] = make_float2(od[nc][2], od[nc][3]);
    }
}

// ------------------- K2b: merge split-K partials (max rescale) -------------------
__global__ void k_merge()
{
    int n = blockIdx.x * 256 + threadIdx.x;
    if (n >= B * N) return;
    float m[SPLITK], sc[SPLITK];
    float M = -1e30f;
    #pragma unroll
    for (int p = 0; p < SPLITK; p++) { m[p] = g_mpart[(size_t)p * (B * N) + n]; M = fmaxf(M, m[p]); }
    float l = 0.f;
    #pragma unroll
    for (int p = 0; p < SPLITK; p++) {
        sc[p] = ex2a(m[p] - M);
        l += g_lpart[(size_t)p * (B * N) + n] * sc[p];
    }
    float inv = 1.f / l;
    float acc[16];
    #pragma unroll
    for (int i = 0; i < 16; i++) acc[i] = 0.f;
    #pragma unroll
    for (int p = 0; p < SPLITK; p++) {
        const float4* a = (const float4*)(g_opart + ((size_t)p * (B * N) + n) * IC);
        #pragma unroll
        for (int i = 0; i < 4; i++) {
            float4 v = a[i];
            acc[i * 4 + 0] += v.x * sc[p]; acc[i * 4 + 1] += v.y * sc[p];
            acc[i * 4 + 2] += v.z * sc[p]; acc[i * 4 + 3] += v.w * sc[p];
        }
    }
    float4* y = (float4*)(g_y + (size_t)n * IC);
    #pragma unroll
    for (int i = 0; i < 4; i++) {
        float4 r;
        r.x = acc[i * 4 + 0] * inv; r.y = acc[i * 4 + 1] * inv;
        r.z = acc[i * 4 + 2] * inv; r.w = acc[i * 4 + 3] * inv;
        y[i] = r;
    }
}

// ------------------- K3: upsample + out conv + residual (register yup, vec Wo) -------------------
// jax scale_and_translate, scale=2, trans=+0.5 => sample_f = 0.5*o - 0.5 (clamped taps)
__global__ void __launch_bounds__(256) k_out(const float* __restrict__ x,
                                             const float* __restrict__ ow,
                                             const float* __restrict__ ob)
{
    __shared__ float yr[16][65];
    __shared__ float Wo[64][16];
    __shared__ float obs[64];

    int b = blockIdx.x >> 7;
    int h = blockIdx.x & 127;
    int t = threadIdx.x;  // 256

    for (int idx = t; idx < 1024; idx += 256) Wo[idx >> 4][idx & 15] = ow[idx];
    if (t < 64) obs[t] = ob[t];

    float fh = 0.5f * (float)h - 0.5f;
    int   ihf = (int)floorf(fh);
    float w1  = fh - (float)ihf;
    int ih0 = ihf < 0 ? 0 : ihf;
    int ih1 = (ihf + 1) > 63 ? 63 : (ihf + 1);

    for (int idx = t; idx < 1024; idx += 256) {
        int i = idx & 15, jw = idx >> 4;      // coalesced g_y reads
        float a = g_y[((size_t)b * N + ih0 * 64 + jw) * IC + i];
        float c = g_y[((size_t)b * N + ih1 * 64 + jw) * IC + i];
        yr[i][jw] = (1.f - w1) * a + w1 * c;
    }
    __syncthreads();

    int w    = t & 127;
    int half = t >> 7;

    float fw = 0.5f * (float)w - 0.5f;
    int   jf = (int)floorf(fw);
    float ww = fw - (float)jf;
    int j0 = jf < 0 ? 0 : jf;
    int j1 = (jf + 1) > 63 ? 63 : (jf + 1);

    float yv[16];
    #pragma unroll
    for (int i = 0; i < 16; i++)
        yv[i] = (1.f - ww) * yr[i][j0] + ww * yr[i][j1];

    const float* xrow = x   + ((size_t)b * C * H + h) * W;
    float*       zrow = g_z + ((size_t)b * C * H + h) * W;

    for (int c = half; c < C; c += 2) {
        float4 w0 = *(float4*)&Wo[c][0];
        float4 w4 = *(float4*)&Wo[c][4];
        float4 w8 = *(float4*)&Wo[c][8];
        float4 wc = *(float4*)&Wo[c][12];
        float s = obs[c];
        s += w0.x * yv[0]  + w0.y * yv[1]  + w0.z * yv[2]  + w0.w * yv[3];
        s += w4.x * yv[4]  + w4.y * yv[5]  + w4.z * yv[6]  + w4.w * yv[7];
        s += w8.x * yv[8]  + w8.y * yv[9]  + w8.z * yv[10] + w8.w * yv[11];
        s += wc.x * yv[12] + wc.y * yv[13] + wc.z * yv[14] + wc.w * yv[15];
        zrow[(size_t)c * (H * W) + w] = xrow[(size_t)c * (H * W) + w] + s;
    }
}

// ------------------- K3b: BN partial reduction over g_z (deterministic) -------------------
__global__ void k_bnred()
{
    __shared__ float ss[8], sq[8];
    int plane = blockIdx.x >> 2;
    int chunk = blockIdx.x & 3;
    int t = threadIdx.x;

    const float4* p = (const float4*)(g_z + (size_t)plane * (H * W) + chunk * 4096);
    float s = 0.f, q = 0.f;
    #pragma unroll
    for (int i = 0; i < 4; i++) {
        float4 v = p[i * 256 + t];
        s += ((v.x + v.y) + (v.z + v.w));
        q += ((v.x * v.x + v.y * v.y) + (v.z * v.z + v.w * v.w));
    }
    #pragma unroll
    for (int off = 16; off; off >>= 1) {
        s += __shfl_down_sync(0xffffffffu, s, off);
        q += __shfl_down_sync(0xffffffffu, q, off);
    }
    int warp = t >> 5, lane = t & 31;
    if (lane == 0) { ss[warp] = s; sq[warp] = q; }
    __syncthreads();
    if (t == 0) {
        float S = ((ss[0] + ss[1]) + (ss[2] + ss[3])) + ((ss[4] + ss[5]) + (ss[6] + ss[7]));
        float Q = ((sq[0] + sq[1]) + (sq[2] + sq[3])) + ((sq[4] + sq[5]) + (sq[6] + sq[7]));
        g_bnpart[((size_t)plane * 4 + chunk) * 2 + 0] = S;
        g_bnpart[((size_t)plane * 4 + chunk) * 2 + 1] = Q;
    }
}

// ------------------- K4: finalize BN stats -------------------
__global__ void k_stats()
{
    int c = threadIdx.x;
    if (c >= C) return;
    float s = 0.f, q = 0.f;
    #pragma unroll
    for (int b = 0; b < B; b++)
        #pragma unroll
        for (int ch = 0; ch < 4; ch++) {
            size_t idx = (((size_t)b * C + c) * 4 + ch) * 2;
            s += g_bnpart[idx + 0];
            q += g_bnpart[idx + 1];
        }
    float mean = s * (1.f / (float)BN_COUNT);
    float var  = q * (1.f / (float)BN_COUNT) - mean * mean;
    g_bnstat[c * 2 + 0] = mean;
    g_bnstat[c * 2 + 1] = rsqrtf(var + 1e-5f);
}

// ------------------- K5: normalize -------------------
__global__ void k_norm(const float* __restrict__ gamma, const float* __restrict__ beta,
                       float* __restrict__ out)
{
    size_t i4 = (size_t)blockIdx.x * 256 + threadIdx.x;
    int c = (int)((i4 >> 12) & 63);
    float mean = g_bnstat[c * 2 + 0];
    float rstd = g_bnstat[c * 2 + 1];
    float ga = gamma[c] * rstd;
    float be = beta[c] - mean * ga;
    float4 z = ((const float4*)g_z)[i4];
    float4 r;
    r.x = z.x * ga + be; r.y = z.y * ga + be;
    r.z = z.z * ga + be; r.w = z.w * ga + be;
    ((float4*)out)[i4] = r;
}

// ------------------------------- launch -------------------------------
extern "C" void kernel_launch(void* const* d_in, const int* in_sizes, int n_in,
                              void* d_out, int out_size)
{
    const float* x     = (const float*)d_in[0];
    const float* g_w   = (const float*)d_in[1];
    const float* g_b   = (const float*)d_in[2];
    const float* th_w  = (const float*)d_in[3];
    const float* th_b  = (const float*)d_in[4];
    const float* ph_w  = (const float*)d_in[5];
    const float* ph_b  = (const float*)d_in[6];
    const float* out_w = (const float*)d_in[7];
    const float* out_b = (const float*)d_in[8];
    const float* gamma = (const float*)d_in[9];
    const float* beta  = (const float*)d_in[10];
    float* out = (float*)d_out;

    k_down_proj<<<B * 64, 256>>>(x, g_w, g_b, th_w, th_b, ph_w, ph_b);
    k_attn<<<B * 64 * SPLITK, 128>>>();
    k_merge<<<64, 256>>>();
    k_out<<<B * H, 256>>>(x, out_w, out_b);
    k_bnred<<<B * C * 4, 256>>>();
    k_stats<<<1, 64>>>();
    k_norm<<<4096, 256>>>(gamma, beta, out);
}